// round 10
// baseline (speedup 1.0000x reference)
#include <cuda_runtime.h>
#include <cuda_fp16.h>
#include <cstdint>

#define MMV 2048
#define NNV 4096
#define KKV 4096

// Scratch (__device__ globals; no allocations allowed)
__device__ __align__(16) __half g_xh[(size_t)MMV * KKV];  // fp16(x)
__device__ __align__(16) __half g_wd[(size_t)KKV * NNV];  // fp16(s*(q-z)), [K][N]

// ---------------------------------------------------------------------------
// asm helpers
// ---------------------------------------------------------------------------
__device__ __forceinline__ void ldsm4(uint32_t* r, uint32_t addr) {
    asm volatile("ldmatrix.sync.aligned.m8n8.x4.shared.b16 {%0,%1,%2,%3}, [%4];"
                 : "=r"(r[0]), "=r"(r[1]), "=r"(r[2]), "=r"(r[3]) : "r"(addr));
}
__device__ __forceinline__ void ldsm4t(uint32_t* r, uint32_t addr) {
    asm volatile("ldmatrix.sync.aligned.m8n8.x4.trans.shared.b16 {%0,%1,%2,%3}, [%4];"
                 : "=r"(r[0]), "=r"(r[1]), "=r"(r[2]), "=r"(r[3]) : "r"(addr));
}
__device__ __forceinline__ void mma_f16(float* c, const uint32_t* a, const uint32_t* b) {
    asm volatile("mma.sync.aligned.m16n8k16.row.col.f32.f16.f16.f32 "
                 "{%0,%1,%2,%3}, {%4,%5,%6,%7}, {%8,%9}, {%0,%1,%2,%3};"
                 : "+f"(c[0]), "+f"(c[1]), "+f"(c[2]), "+f"(c[3])
                 : "r"(a[0]), "r"(a[1]), "r"(a[2]), "r"(a[3]), "r"(b[0]), "r"(b[1]));
}
__device__ __forceinline__ void cpa16(uint32_t s, const void* g) {
    asm volatile("cp.async.cg.shared.global [%0], [%1], 16;" :: "r"(s), "l"(g));
}
#define CP_COMMIT() asm volatile("cp.async.commit_group;" ::: "memory")
#define CP_WAIT2()  asm volatile("cp.async.wait_group 2;" ::: "memory")

// ---------------------------------------------------------------------------
// Fused prep.
// blocks [0,8192):      x -> fp16
// blocks [8192,12288):  W unpack, n-pair layout -> coalesced half2 stores
// ---------------------------------------------------------------------------
__global__ void prep_kernel(const float4* __restrict__ x4,
                            const int* __restrict__ qw,
                            const float* __restrict__ zp,
                            const float* __restrict__ scales)
{
    if (blockIdx.x < 8192) {
        size_t i = (size_t)blockIdx.x * blockDim.x + threadIdx.x;   // over M*K/4
        float4 v = x4[i];
        __align__(8) __half h[4];
        h[0] = __float2half_rn(v.x); h[1] = __float2half_rn(v.y);
        h[2] = __float2half_rn(v.z); h[3] = __float2half_rn(v.w);
        ((uint2*)g_xh)[i] = *(uint2*)h;
    } else {
        // thread handles one kp (8 k's) and an n-pair
        int T = (blockIdx.x - 8192) * blockDim.x + threadIdx.x;     // < 512*2048
        int np = T & (NNV / 2 - 1);          // n-pair index
        int kp = T >> 11;
        int g  = kp >> 4;
        int n0 = np * 2;
        float z0 = fminf(fmaxf(rintf(zp[g * NNV + n0]),     0.0f), 15.0f);
        float z1 = fminf(fmaxf(rintf(zp[g * NNV + n0 + 1]), 0.0f), 15.0f);
        float s0 = fminf(fmaxf(scales[g * NNV + n0],     1e-5f), 1e4f);
        float s1 = fminf(fmaxf(scales[g * NNV + n0 + 1], 1e-5f), 1e4f);
        int q0 = qw[(size_t)kp * NNV + n0];
        int q1 = qw[(size_t)kp * NNV + n0 + 1];
#pragma unroll
        for (int j = 0; j < 8; ++j) {
            float w0 = (float)((q0 >> (4 * j)) & 15);
            float w1 = (float)((q1 >> (4 * j)) & 15);
            __half2 o = __floats2half2_rn((w0 - z0) * s0, (w1 - z1) * s1);
            *(__half2*)(g_wd + (size_t)(kp * 8 + j) * NNV + n0) = o;
        }
    }
}

// ---------------------------------------------------------------------------
// GEMM: C = xh @ Wd + bias.  Plain fp16 GEMM, fp32 accum.
// CTA tile 64x64, BK=64, 4 warps (2m x 2n), warp tile 32x32.
// 2048 CTAs -> 4.61 waves over 444 slots (vs 2.31 at 64x128): tail-wave
// utilization 77% -> 92%.
// NS=4 stages x (A 8K | B 8K) = 64 KB smem; 3 CTAs/SM.
// ---------------------------------------------------------------------------
#define NS 4
#define STG_BYTES 16384
#define SMEM_TOTAL (NS * STG_BYTES)   // 65536

__global__ void __launch_bounds__(128, 3)
gemm_kernel(const float* __restrict__ bias,
            float* __restrict__ C)
{
    extern __shared__ __align__(16) char smem[];
    const uint32_t sb = (uint32_t)__cvta_generic_to_shared(smem);
    const int tid = threadIdx.x, lane = tid & 31, wid = tid >> 5;
    const int wm = wid & 1, wn = wid >> 1;
    const int m0 = blockIdx.y * 64, n0 = blockIdx.x * 64;

    // loader: A 64x64 fp16 (512 x 16B chunks), B 64x64 fp16 (512 chunks)
    auto load_stage = [&](int kt, int st) {
        uint32_t base = sb + st * STG_BYTES;
#pragma unroll
        for (int j = 0; j < 4; ++j) {
            int q = tid + j * 128;
            int r = q >> 3, c = q & 7;
            uint32_t so = (uint32_t)(r * 8 + (c ^ (r & 7))) * 16;
            cpa16(base + so,        g_xh + (size_t)(m0 + r) * KKV + kt * 64 + c * 8);
            cpa16(base + 8192 + so, g_wd + (size_t)(kt * 64 + r) * NNV + n0 + c * 8);
        }
    };

    // prefill NS-1 = 3 stages
    load_stage(0, 0); CP_COMMIT();
    load_stage(1, 1); CP_COMMIT();
    load_stage(2, 2); CP_COMMIT();

    // ldmatrix address precompute
    const int lane_r = lane & 15, chh = lane >> 4;
    uint32_t arow[2], axr[2];
#pragma unroll
    for (int t = 0; t < 2; ++t) {
        int r = wm * 32 + t * 16 + lane_r;
        arow[t] = (uint32_t)r * 128;            // 128 B per A row
        axr[t]  = (uint32_t)(r & 7);
    }
    const uint32_t xb = (uint32_t)(lane_r & 7);
    uint32_t bcol[2];
#pragma unroll
    for (int bb = 0; bb < 2; ++bb)
        bcol[bb] = (uint32_t)(((uint32_t)(wn * 4 + bb * 2 + chh)) ^ xb) * 16;
    uint32_t boff[4];
#pragma unroll
    for (int ks = 0; ks < 4; ++ks)
        boff[ks] = (uint32_t)(ks * 16 + lane_r) * 128;   // 128 B per B row

    float accM[2][4][4];
#pragma unroll
    for (int t = 0; t < 2; ++t)
#pragma unroll
        for (int nt = 0; nt < 4; ++nt)
#pragma unroll
            for (int i = 0; i < 4; ++i) accM[t][nt][i] = 0.f;

    int st = 0, stn = 3;   // rotating stage indices: current, next-to-load
    for (int kt = 0; kt < 64; ++kt) {
        CP_WAIT2();
        __syncthreads();

        const uint32_t Ab = sb + st * STG_BYTES;
        const uint32_t Bb = Ab + 8192;

        if (kt + 3 < 64) load_stage(kt + 3, stn);
        CP_COMMIT();

#pragma unroll
        for (int ks = 0; ks < 4; ++ks) {
            uint32_t af[2][4], bfr[2][4];
#pragma unroll
            for (int t = 0; t < 2; ++t) {
                uint32_t co = ((uint32_t)(ks * 2 + chh) ^ axr[t]) * 16;
                ldsm4(af[t], Ab + arow[t] + co);
            }
#pragma unroll
            for (int bb = 0; bb < 2; ++bb)
                ldsm4t(bfr[bb], Bb + boff[ks] + bcol[bb]);
#pragma unroll
            for (int t = 0; t < 2; ++t)
#pragma unroll
                for (int nt = 0; nt < 4; ++nt)
                    mma_f16(accM[t][nt], af[t], &bfr[nt >> 1][(nt & 1) * 2]);
        }

        st  = (st  == NS - 1) ? 0 : st + 1;
        stn = (stn == NS - 1) ? 0 : stn + 1;
    }

    // epilogue
#pragma unroll
    for (int t = 0; t < 2; ++t) {
        int row0 = m0 + wm * 32 + t * 16 + (lane >> 2);
#pragma unroll
        for (int nt = 0; nt < 4; ++nt) {
            int col = n0 + wn * 32 + nt * 8 + (lane & 3) * 2;
            float2 b = *(const float2*)(bias + col);
            float2 o0, o1;
            o0.x = accM[t][nt][0] + b.x;  o0.y = accM[t][nt][1] + b.y;
            o1.x = accM[t][nt][2] + b.x;  o1.y = accM[t][nt][3] + b.y;
            *(float2*)(C + (size_t)row0 * NNV + col)       = o0;
            *(float2*)(C + (size_t)(row0 + 8) * NNV + col) = o1;
        }
    }
}

// ---------------------------------------------------------------------------
// Host. Inputs: x, scales, zero_points, bias, qweight
// ---------------------------------------------------------------------------
extern "C" void kernel_launch(void* const* d_in, const int* in_sizes, int n_in,
                              void* d_out, int out_size)
{
    const float* x      = (const float*)d_in[0];
    const float* scales = (const float*)d_in[1];
    const float* zp     = (const float*)d_in[2];
    const float* bias   = (const float*)d_in[3];
    const int*   qw     = (const int*)d_in[4];
    float*       out    = (float*)d_out;

    prep_kernel<<<12288, 256>>>((const float4*)x, qw, zp, scales);

    static bool attr_set = false;
    if (!attr_set) {
        cudaFuncSetAttribute(gemm_kernel, cudaFuncAttributeMaxDynamicSharedMemorySize, SMEM_TOTAL);
        attr_set = true;
    }
    gemm_kernel<<<dim3(NNV / 64, MMV / 64), 128, SMEM_TOTAL>>>(bias, out);
}